// round 1
// baseline (speedup 1.0000x reference)
#include <cuda_runtime.h>
#include <cuda_bf16.h>
#include <math.h>

// ---------------- Problem dims ----------------
#define BB 512
#define TT 512
#define VV 50000
#define EE 100
#define HH 40
// gates = 3H = 120

// ---------------- Device scratch ----------------
__device__ float g_embW0[VV * 240];          // [v][0..119]=fwd gates(Wih0f@emb+bih0f), [120..239]=bwd
__device__ float g_out0[BB * TT * 80];       // layer0 output, [b][t][0..39]=fwd, [40..79]=bwd
__device__ float g_Wih0T[EE * 240];          // [k][j] packed fwd|bwd
__device__ float g_bih0cat[240];
__device__ float g_WhhT0f[40 * 120], g_WhhT0b[40 * 120];   // [k][j]
__device__ float g_Wih1fT[80 * 120], g_Wih1bT[80 * 120];   // [k][j]
__device__ float g_Whh1fT[40 * 120], g_Whh1bT[40 * 120];   // [k][j]
__device__ float g_fc1WT[320 * 128];                       // [k][i]
__device__ float g_hf0[BB * HH], g_hb0[BB * HH], g_hf1[BB * HH], g_hb1[BB * HH];
__device__ float g_avgp[BB * 80], g_maxp[BB * 80];

// ---------------- Prep: transpose / pack all weights ----------------
__global__ void prep_weights(
    const float* __restrict__ Wih0f, const float* __restrict__ Whh0f,
    const float* __restrict__ bih0f,
    const float* __restrict__ Wih0b, const float* __restrict__ Whh0b,
    const float* __restrict__ bih0b,
    const float* __restrict__ Wih1f, const float* __restrict__ Whh1f,
    const float* __restrict__ Wih1b, const float* __restrict__ Whh1b,
    const float* __restrict__ fc1_W)
{
    int g = blockIdx.x * blockDim.x + threadIdx.x;
    int NT = gridDim.x * blockDim.x;
    // Wih0T [100][240]
    for (int i = g; i < EE * 240; i += NT) {
        int k = i / 240, j = i % 240;
        g_Wih0T[i] = (j < 120) ? Wih0f[j * EE + k] : Wih0b[(j - 120) * EE + k];
    }
    for (int i = g; i < 240; i += NT)
        g_bih0cat[i] = (i < 120) ? bih0f[i] : bih0b[i - 120];
    // WhhT0 [40][120]
    for (int i = g; i < 40 * 120; i += NT) {
        int k = i / 120, j = i % 120;
        g_WhhT0f[i] = Whh0f[j * 40 + k];
        g_WhhT0b[i] = Whh0b[j * 40 + k];
        g_Whh1fT[i] = Whh1f[j * 40 + k];
        g_Whh1bT[i] = Whh1b[j * 40 + k];
    }
    // Wih1T [80][120]
    for (int i = g; i < 80 * 120; i += NT) {
        int k = i / 120, j = i % 120;
        g_Wih1fT[i] = Wih1f[j * 80 + k];
        g_Wih1bT[i] = Wih1b[j * 80 + k];
    }
    // fc1WT [320][128]
    for (int i = g; i < 320 * 128; i += NT) {
        int k = i / 128, q = i % 128;
        g_fc1WT[i] = fc1_W[q * 320 + k];
    }
}

// ---------------- embW GEMM: [50000,100] x [100,240] + bias ----------------
// block: 256 threads, tile 64 vocab rows x 240 cols; thread j owns column j, 64 row-accumulators
__global__ void __launch_bounds__(256) embw_kernel(const float* __restrict__ emb)
{
    int j = threadIdx.x;            // 0..255, active < 240
    int v0 = blockIdx.x * 64;
    int rows = VV - v0; if (rows > 64) rows = 64;
    __shared__ __align__(16) float A_s[20][68];  // [k][r], padded

    float acc[64];
    float bias = (j < 240) ? g_bih0cat[j] : 0.f;
    #pragma unroll
    for (int r = 0; r < 64; r++) acc[r] = bias;

    for (int k0 = 0; k0 < EE; k0 += 20) {
        __syncthreads();
        for (int idx = threadIdx.x; idx < 64 * 20; idx += 256) {
            int r = idx / 20, k = idx % 20;
            A_s[k][r] = (r < rows) ? emb[(size_t)(v0 + r) * EE + k0 + k] : 0.f;
        }
        __syncthreads();
        if (j < 240) {
            #pragma unroll
            for (int k = 0; k < 20; k++) {
                float bval = g_Wih0T[(k0 + k) * 240 + j];
                const float4* ap = (const float4*)(&A_s[k][0]);
                #pragma unroll
                for (int r4 = 0; r4 < 16; r4++) {
                    float4 a = ap[r4];
                    acc[4 * r4 + 0] = fmaf(a.x, bval, acc[4 * r4 + 0]);
                    acc[4 * r4 + 1] = fmaf(a.y, bval, acc[4 * r4 + 1]);
                    acc[4 * r4 + 2] = fmaf(a.z, bval, acc[4 * r4 + 2]);
                    acc[4 * r4 + 3] = fmaf(a.w, bval, acc[4 * r4 + 3]);
                }
            }
        }
    }
    if (j < 240) {
        #pragma unroll
        for (int r = 0; r < 64; r++)
            if (r < rows) g_embW0[(size_t)(v0 + r) * 240 + j] = acc[r];
    }
}

__device__ __forceinline__ float sigmoidf_(float x) { return 1.f / (1.f + expf(-x)); }

// ---------------- Layer 0 recurrence (one block per (batch, dir)) ----------------
__global__ void __launch_bounds__(128) gru_layer0(
    const int* __restrict__ text, const int* __restrict__ lens,
    const float* __restrict__ bhh0f, const float* __restrict__ bhh0b)
{
    int b = blockIdx.x, dir = blockIdx.y;
    int j = threadIdx.x;
    __shared__ __align__(16) float h_s[40];
    __shared__ float srz[80], gxn_s[40], ghn_s[40];
    __shared__ int toks[TT];

    int len = lens[b];
    for (int i = j; i < TT; i += 128) toks[i] = text[b * TT + i];

    const float* whhT = dir ? g_WhhT0b : g_WhhT0f;
    float w[40];
    float bhh_j = 0.f;
    if (j < 120) {
        #pragma unroll
        for (int k = 0; k < 40; k++) w[k] = whhT[k * 120 + j];
        bhh_j = (dir ? bhh0b : bhh0f)[j];
    }
    if (j < 40) h_s[j] = 0.f;
    __syncthreads();

    const float* embW = g_embW0 + dir * 120;
    int t0 = dir ? (len - 1) : 0;
    int td = dir ? -1 : 1;
    float gx = (j < 120) ? embW[(size_t)toks[t0] * 240 + j] : 0.f;

    for (int s = 0; s < len; s++) {
        int t = t0 + s * td;
        float gx_next = 0.f;
        if (j < 120 && s + 1 < len) gx_next = embW[(size_t)toks[t + td] * 240 + j];
        if (j < 120) {
            float a0 = bhh_j, a1 = 0.f, a2 = 0.f, a3 = 0.f;
            const float4* h4 = (const float4*)h_s;
            #pragma unroll
            for (int k = 0; k < 10; k++) {
                float4 hv = h4[k];
                a0 = fmaf(w[4 * k + 0], hv.x, a0);
                a1 = fmaf(w[4 * k + 1], hv.y, a1);
                a2 = fmaf(w[4 * k + 2], hv.z, a2);
                a3 = fmaf(w[4 * k + 3], hv.w, a3);
            }
            float acc = (a0 + a1) + (a2 + a3);
            if (j < 80) srz[j] = gx + acc;
            else { gxn_s[j - 80] = gx; ghn_s[j - 80] = acc; }
        }
        __syncthreads();
        if (j < 40) {
            float r = sigmoidf_(srz[j]);
            float z = sigmoidf_(srz[40 + j]);
            float n = tanhf(fmaf(r, ghn_s[j], gxn_s[j]));
            float hn = fmaf(z, h_s[j] - n, n);   // (1-z)*n + z*h
            h_s[j] = hn;
            g_out0[((size_t)b * TT + t) * 80 + dir * 40 + j] = hn;
        }
        __syncthreads();
        gx = gx_next;
    }
    if (j < 40) (dir ? g_hb0 : g_hf0)[b * HH + j] = h_s[j];
}

// ---------------- Layer 1 recurrence with fused input GEMM + fused pooling ----------------
__global__ void __launch_bounds__(128, 3) gru_layer1(
    const int* __restrict__ lens,
    const float* __restrict__ bih1f, const float* __restrict__ bhh1f,
    const float* __restrict__ bih1b, const float* __restrict__ bhh1b)
{
    int b = blockIdx.x, dir = blockIdx.y;
    int j = threadIdx.x;
    __shared__ __align__(16) float h_s[40];
    __shared__ __align__(16) float x_s[80];
    __shared__ float srz[80], gxn_s[40], ghn_s[40];

    int len = lens[b];
    const float* wihT = dir ? g_Wih1bT : g_Wih1fT;
    const float* whhT = dir ? g_Whh1bT : g_Whh1fT;
    float wi[80], wh[40];
    float bih_j = 0.f, bhh_j = 0.f;
    if (j < 120) {
        #pragma unroll
        for (int k = 0; k < 80; k++) wi[k] = wihT[k * 120 + j];
        #pragma unroll
        for (int k = 0; k < 40; k++) wh[k] = whhT[k * 120 + j];
        bih_j = (dir ? bih1b : bih1f)[j];
        bhh_j = (dir ? bhh1b : bhh1f)[j];
    }
    if (j < 40) h_s[j] = 0.f;
    int t0 = dir ? (len - 1) : 0;
    int td = dir ? -1 : 1;
    if (j < 80) x_s[j] = g_out0[((size_t)b * TT + t0) * 80 + j];
    __syncthreads();

    float sum_p = 0.f, max_p = -1e30f;

    for (int s = 0; s < len; s++) {
        int t = t0 + s * td;
        if (j < 120) {
            float ax0 = bih_j, ax1 = 0.f, ax2 = 0.f, ax3 = 0.f;
            const float4* x4 = (const float4*)x_s;
            #pragma unroll
            for (int k = 0; k < 20; k++) {
                float4 xv = x4[k];
                ax0 = fmaf(wi[4 * k + 0], xv.x, ax0);
                ax1 = fmaf(wi[4 * k + 1], xv.y, ax1);
                ax2 = fmaf(wi[4 * k + 2], xv.z, ax2);
                ax3 = fmaf(wi[4 * k + 3], xv.w, ax3);
            }
            float ah0 = bhh_j, ah1 = 0.f, ah2 = 0.f, ah3 = 0.f;
            const float4* h4 = (const float4*)h_s;
            #pragma unroll
            for (int k = 0; k < 10; k++) {
                float4 hv = h4[k];
                ah0 = fmaf(wh[4 * k + 0], hv.x, ah0);
                ah1 = fmaf(wh[4 * k + 1], hv.y, ah1);
                ah2 = fmaf(wh[4 * k + 2], hv.z, ah2);
                ah3 = fmaf(wh[4 * k + 3], hv.w, ah3);
            }
            float accx = (ax0 + ax1) + (ax2 + ax3);
            float acch = (ah0 + ah1) + (ah2 + ah3);
            if (j < 80) srz[j] = accx + acch;
            else { gxn_s[j - 80] = accx; ghn_s[j - 80] = acch; }
        }
        __syncthreads();
        if (j < 40) {
            float r = sigmoidf_(srz[j]);
            float z = sigmoidf_(srz[40 + j]);
            float n = tanhf(fmaf(r, ghn_s[j], gxn_s[j]));
            float hn = fmaf(z, h_s[j] - n, n);
            h_s[j] = hn;
            sum_p += hn;
            max_p = fmaxf(max_p, hn);
        } else if (j < 120 && s + 1 < len) {
            int idx = j - 40;
            x_s[idx] = g_out0[((size_t)b * TT + (t + td)) * 80 + idx];
        }
        __syncthreads();
    }
    if (j < 40) {
        g_avgp[b * 80 + dir * 40 + j] = sum_p / (float)len;
        g_maxp[b * 80 + dir * 40 + j] = max_p;
        (dir ? g_hb1 : g_hf1)[b * HH + j] = h_s[j];
    }
}

// ---------------- Head: pool_cat -> fc1 -> leaky -> fc2 ----------------
__global__ void __launch_bounds__(128) fc_kernel(
    const float* __restrict__ fc1_b, const float* __restrict__ fc2_W,
    const float* __restrict__ fc2_b, float* __restrict__ out)
{
    int b = blockIdx.x, j = threadIdx.x;
    __shared__ float cat[320];
    for (int i = j; i < 320; i += 128) {
        float v;
        if (i < 40)       v = g_hb1[b * 40 + i];
        else if (i < 80)  v = g_hf1[b * 40 + (i - 40)];
        else if (i < 120) v = g_hb0[b * 40 + (i - 80)];
        else if (i < 160) v = g_hf0[b * 40 + (i - 120)];
        else if (i < 240) v = g_avgp[b * 80 + (i - 160)];
        else              v = g_maxp[b * 80 + (i - 240)];
        cat[i] = v;
    }
    __syncthreads();
    float acc = fc1_b[j];
    #pragma unroll 8
    for (int k = 0; k < 320; k++)
        acc = fmaf(g_fc1WT[k * 128 + j], cat[k], acc);
    float h = (acc >= 0.f) ? acc : 0.01f * acc;
    float p = h * fc2_W[j];
    #pragma unroll
    for (int o = 16; o > 0; o >>= 1) p += __shfl_down_sync(0xffffffffu, p, o);
    __shared__ float red[4];
    if ((j & 31) == 0) red[j >> 5] = p;
    __syncthreads();
    if (j == 0) out[b] = (red[0] + red[1] + red[2] + red[3]) + fc2_b[0];
}

// ---------------- Launch ----------------
extern "C" void kernel_launch(void* const* d_in, const int* in_sizes, int n_in,
                              void* d_out, int out_size)
{
    const int*   text     = (const int*)d_in[0];
    const int*   text_len = (const int*)d_in[1];
    const float* emb      = (const float*)d_in[2];
    const float* Wih0f = (const float*)d_in[3];
    const float* Whh0f = (const float*)d_in[4];
    const float* bih0f = (const float*)d_in[5];
    const float* bhh0f = (const float*)d_in[6];
    const float* Wih0b = (const float*)d_in[7];
    const float* Whh0b = (const float*)d_in[8];
    const float* bih0b = (const float*)d_in[9];
    const float* bhh0b = (const float*)d_in[10];
    const float* Wih1f = (const float*)d_in[11];
    const float* Whh1f = (const float*)d_in[12];
    const float* bih1f = (const float*)d_in[13];
    const float* bhh1f = (const float*)d_in[14];
    const float* Wih1b = (const float*)d_in[15];
    const float* Whh1b = (const float*)d_in[16];
    const float* bih1b = (const float*)d_in[17];
    const float* bhh1b = (const float*)d_in[18];
    const float* fc1_W = (const float*)d_in[19];
    const float* fc1_b = (const float*)d_in[20];
    const float* fc2_W = (const float*)d_in[21];
    const float* fc2_b = (const float*)d_in[22];
    float* out = (float*)d_out;

    prep_weights<<<160, 256>>>(Wih0f, Whh0f, bih0f, Wih0b, Whh0b, bih0b,
                               Wih1f, Whh1f, Wih1b, Whh1b, fc1_W);
    embw_kernel<<<(VV + 63) / 64, 256>>>(emb);
    gru_layer0<<<dim3(BB, 2), 128>>>(text, text_len, bhh0f, bhh0b);
    gru_layer1<<<dim3(BB, 2), 128>>>(text_len, bih1f, bhh1f, bih1b, bhh1b);
    fc_kernel<<<BB, 128>>>(fc1_b, fc2_W, fc2_b, out);
}

// round 2
// speedup vs baseline: 1.4809x; 1.4809x over previous
#include <cuda_runtime.h>
#include <cuda_bf16.h>
#include <math.h>

// ---------------- Problem dims ----------------
#define BB 512
#define TT 512
#define VV 50000
#define EE 100
#define HH 40
// gates = 3H = 120

typedef unsigned long long u64;

// ---------------- f32x2 packed helpers ----------------
__device__ __forceinline__ u64 f2u2(float x, float y) {
    u64 u; asm("mov.b64 %0, {%1,%2};" : "=l"(u) : "f"(x), "f"(y)); return u;
}
__device__ __forceinline__ u64 fma2(u64 a, u64 b, u64 c) {
    u64 d; asm("fma.rn.f32x2 %0, %1, %2, %3;" : "=l"(d) : "l"(a), "l"(b), "l"(c)); return d;
}
__device__ __forceinline__ float2 u2f2(u64 u) {
    float lo, hi; asm("mov.b64 {%0,%1}, %2;" : "=f"(lo), "=f"(hi) : "l"(u));
    return make_float2(lo, hi);
}

__device__ __forceinline__ float sigf(float x) {
    return __fdividef(1.f, 1.f + __expf(-x));
}
__device__ __forceinline__ float tanh_fast(float x) {
    float a = fminf(fmaxf(-2.f * x, -80.f), 80.f);
    float e = __expf(a);
    return __fdividef(1.f - e, 1.f + e);
}

// ---------------- Device scratch ----------------
__device__ __align__(16) float g_embW0[VV * 240];     // [v][fwd 120 | bwd 120] gates = Wih0@emb+bih0
__device__ __align__(16) float g_out0[BB * TT * 80];  // layer0 out, [b][t][fwd40|bwd40]
__device__ __align__(16) float g_Wih0T[EE * 240];
__device__ __align__(16) float g_bih0cat[240];
// pair-packed recurrence weights: P[(k2*120 + j)*2 + c] = W[j][2*k2+c]
__device__ __align__(16) float g_Whh0fP[20 * 120 * 2], g_Whh0bP[20 * 120 * 2];
__device__ __align__(16) float g_Wih1fP[40 * 120 * 2], g_Wih1bP[40 * 120 * 2];
__device__ __align__(16) float g_Whh1fP[20 * 120 * 2], g_Whh1bP[20 * 120 * 2];
__device__ __align__(16) float g_fc1WT[320 * 128];
__device__ float g_hf0[BB * HH], g_hb0[BB * HH], g_hf1[BB * HH], g_hb1[BB * HH];
__device__ float g_avgp[BB * 80], g_maxp[BB * 80];
__device__ int g_perm[BB];

// ---------------- Prep: transpose / pack all weights ----------------
__global__ void prep_weights(
    const float* __restrict__ Wih0f, const float* __restrict__ Whh0f,
    const float* __restrict__ bih0f,
    const float* __restrict__ Wih0b, const float* __restrict__ Whh0b,
    const float* __restrict__ bih0b,
    const float* __restrict__ Wih1f, const float* __restrict__ Whh1f,
    const float* __restrict__ Wih1b, const float* __restrict__ Whh1b,
    const float* __restrict__ fc1_W)
{
    int g = blockIdx.x * blockDim.x + threadIdx.x;
    int NT = gridDim.x * blockDim.x;
    for (int i = g; i < EE * 240; i += NT) {
        int k = i / 240, j = i % 240;
        g_Wih0T[i] = (j < 120) ? Wih0f[j * EE + k] : Wih0b[(j - 120) * EE + k];
    }
    for (int i = g; i < 240; i += NT)
        g_bih0cat[i] = (i < 120) ? bih0f[i] : bih0b[i - 120];
    // Whh packs (both layers): 20 pairs x 120 gates x 2
    for (int i = g; i < 20 * 120 * 2; i += NT) {
        int c = i & 1, t = i >> 1;
        int k2 = t / 120, j = t % 120;
        int src = j * 40 + 2 * k2 + c;
        g_Whh0fP[i] = Whh0f[src];
        g_Whh0bP[i] = Whh0b[src];
        g_Whh1fP[i] = Whh1f[src];
        g_Whh1bP[i] = Whh1b[src];
    }
    // Wih1 packs: 40 pairs x 120 gates x 2
    for (int i = g; i < 40 * 120 * 2; i += NT) {
        int c = i & 1, t = i >> 1;
        int k2 = t / 120, j = t % 120;
        int src = j * 80 + 2 * k2 + c;
        g_Wih1fP[i] = Wih1f[src];
        g_Wih1bP[i] = Wih1b[src];
    }
    for (int i = g; i < 320 * 128; i += NT) {
        int k = i / 128, q = i % 128;
        g_fc1WT[i] = fc1_W[q * 320 + k];
    }
}

// ---------------- Length sort (descending) for load balance ----------------
__global__ void sort_kernel(const int* __restrict__ lens)
{
    __shared__ int L[BB];
    int b = threadIdx.x;
    int lb = lens[b];
    L[b] = lb;
    __syncthreads();
    int r = 0;
    #pragma unroll 8
    for (int i = 0; i < BB; i++) {
        int li = L[i];
        r += (li > lb) || (li == lb && i < b);
    }
    g_perm[r] = b;
}

// ---------------- embW GEMM: [50000,100] x [100,240] + bias ----------------
__global__ void __launch_bounds__(256) embw_kernel(const float* __restrict__ emb)
{
    int j = threadIdx.x;
    int v0 = blockIdx.x * 64;
    int rows = VV - v0; if (rows > 64) rows = 64;
    __shared__ __align__(16) float A_s[20][68];

    float acc[64];
    float bias = (j < 240) ? g_bih0cat[j] : 0.f;
    #pragma unroll
    for (int r = 0; r < 64; r++) acc[r] = bias;

    for (int k0 = 0; k0 < EE; k0 += 20) {
        __syncthreads();
        for (int idx = threadIdx.x; idx < 64 * 20; idx += 256) {
            int r = idx / 20, k = idx % 20;
            A_s[k][r] = (r < rows) ? emb[(size_t)(v0 + r) * EE + k0 + k] : 0.f;
        }
        __syncthreads();
        if (j < 240) {
            #pragma unroll
            for (int k = 0; k < 20; k++) {
                float bval = g_Wih0T[(k0 + k) * 240 + j];
                const float4* ap = (const float4*)(&A_s[k][0]);
                #pragma unroll
                for (int r4 = 0; r4 < 16; r4++) {
                    float4 a = ap[r4];
                    acc[4 * r4 + 0] = fmaf(a.x, bval, acc[4 * r4 + 0]);
                    acc[4 * r4 + 1] = fmaf(a.y, bval, acc[4 * r4 + 1]);
                    acc[4 * r4 + 2] = fmaf(a.z, bval, acc[4 * r4 + 2]);
                    acc[4 * r4 + 3] = fmaf(a.w, bval, acc[4 * r4 + 3]);
                }
            }
        }
    }
    if (j < 240) {
        #pragma unroll
        for (int r = 0; r < 64; r++)
            if (r < rows) g_embW0[(size_t)(v0 + r) * 240 + j] = acc[r];
    }
}

// ---------------- Layer 0 recurrence ----------------
__global__ void __launch_bounds__(128) gru_layer0(
    const int* __restrict__ text, const int* __restrict__ lens,
    const float* __restrict__ bhh0f, const float* __restrict__ bhh0b)
{
    int b = g_perm[blockIdx.x];
    int dir = blockIdx.y;
    int j = threadIdx.x;
    __shared__ __align__(16) float h_s[40];
    __shared__ float srz[80], gxn_s[40], ghn_s[40];
    __shared__ int toks[TT];

    int len = lens[b];
    for (int i = j; i < len; i += 128) toks[i] = text[b * TT + i];

    const u64* wp = (const u64*)(dir ? g_Whh0bP : g_Whh0fP);
    u64 w2[20];
    float bhh_j = 0.f;
    if (j < 120) {
        #pragma unroll
        for (int k2 = 0; k2 < 20; k2++) w2[k2] = wp[k2 * 120 + j];
        bhh_j = (dir ? bhh0b : bhh0f)[j];
    }
    if (j < 40) h_s[j] = 0.f;
    __syncthreads();

    const float* embW = g_embW0 + dir * 120;
    int t0 = dir ? (len - 1) : 0;
    int td = dir ? -1 : 1;

    float gx_cur = 0.f, gx_n1 = 0.f;
    if (j < 120) {
        gx_cur = embW[(size_t)toks[t0] * 240 + j];
        if (len > 1) gx_n1 = embW[(size_t)toks[t0 + td] * 240 + j];
    }

    size_t outbase = ((size_t)b * TT) * 80 + dir * 40 + j;

    for (int s = 0; s < len; s++) {
        int t = t0 + s * td;
        float gx_n2 = 0.f;
        if (j < 120 && s + 2 < len)
            gx_n2 = embW[(size_t)toks[t0 + (s + 2) * td] * 240 + j];
        if (j < 120) {
            u64 acc2 = f2u2(bhh_j, 0.f);
            const u64* h2 = (const u64*)h_s;
            #pragma unroll
            for (int k2 = 0; k2 < 20; k2++)
                acc2 = fma2(w2[k2], h2[k2], acc2);
            float2 a = u2f2(acc2);
            float acc = a.x + a.y;
            if (j < 80) srz[j] = gx_cur + acc;
            else { gxn_s[j - 80] = gx_cur; ghn_s[j - 80] = acc; }
        }
        __syncthreads();
        if (j < 40) {
            float r = sigf(srz[j]);
            float z = sigf(srz[40 + j]);
            float n = tanh_fast(fmaf(r, ghn_s[j], gxn_s[j]));
            float hn = fmaf(z, h_s[j] - n, n);
            h_s[j] = hn;
            g_out0[outbase + (size_t)t * 80] = hn;
        }
        __syncthreads();
        gx_cur = gx_n1;
        gx_n1 = gx_n2;
    }
    if (j < 40) (dir ? g_hb0 : g_hf0)[b * HH + j] = h_s[j];
}

// ---------------- Layer 1 recurrence (fused input GEMM + pooling) ----------------
__global__ void __launch_bounds__(128, 3) gru_layer1(
    const int* __restrict__ lens,
    const float* __restrict__ bih1f, const float* __restrict__ bhh1f,
    const float* __restrict__ bih1b, const float* __restrict__ bhh1b)
{
    int b = g_perm[blockIdx.x];
    int dir = blockIdx.y;
    int j = threadIdx.x;
    __shared__ __align__(16) float h_s[40];
    __shared__ __align__(16) float x_s[80];
    __shared__ float srz[80], gxn_s[40], ghn_s[40];

    int len = lens[b];
    const u64* wip = (const u64*)(dir ? g_Wih1bP : g_Wih1fP);
    const u64* whp = (const u64*)(dir ? g_Whh1bP : g_Whh1fP);
    u64 wi2[40], wh2[20];
    float bih_j = 0.f, bhh_j = 0.f;
    if (j < 120) {
        #pragma unroll
        for (int k2 = 0; k2 < 40; k2++) wi2[k2] = wip[k2 * 120 + j];
        #pragma unroll
        for (int k2 = 0; k2 < 20; k2++) wh2[k2] = whp[k2 * 120 + j];
        bih_j = (dir ? bih1b : bih1f)[j];
        bhh_j = (dir ? bhh1b : bhh1f)[j];
    }
    if (j < 40) h_s[j] = 0.f;

    int t0 = dir ? (len - 1) : 0;
    int td = dir ? -1 : 1;
    const float* xbase = g_out0 + (size_t)b * TT * 80;

    bool loader = (j >= 40 && j < 120);
    int li = j - 40;
    if (j < 80) x_s[j] = xbase[(size_t)t0 * 80 + j];
    float xr_n1 = 0.f;
    if (loader && len > 1) xr_n1 = xbase[(size_t)(t0 + td) * 80 + li];
    __syncthreads();

    float sum_p = 0.f, max_p = -1e30f;

    for (int s = 0; s < len; s++) {
        float xr_n2 = 0.f;
        if (loader && s + 2 < len)
            xr_n2 = xbase[(size_t)(t0 + (s + 2) * td) * 80 + li];
        if (j < 120) {
            u64 accx = f2u2(bih_j, 0.f);
            u64 acch = f2u2(bhh_j, 0.f);
            const u64* x2 = (const u64*)x_s;
            const u64* h2 = (const u64*)h_s;
            #pragma unroll
            for (int k2 = 0; k2 < 40; k2++)
                accx = fma2(wi2[k2], x2[k2], accx);
            #pragma unroll
            for (int k2 = 0; k2 < 20; k2++)
                acch = fma2(wh2[k2], h2[k2], acch);
            float2 axp = u2f2(accx);
            float2 ahp = u2f2(acch);
            float ax = axp.x + axp.y;
            float ah = ahp.x + ahp.y;
            if (j < 80) srz[j] = ax + ah;
            else { gxn_s[j - 80] = ax; ghn_s[j - 80] = ah; }
        }
        __syncthreads();
        if (j < 40) {
            float r = sigf(srz[j]);
            float z = sigf(srz[40 + j]);
            float n = tanh_fast(fmaf(r, ghn_s[j], gxn_s[j]));
            float hn = fmaf(z, h_s[j] - n, n);
            h_s[j] = hn;
            sum_p += hn;
            max_p = fmaxf(max_p, hn);
        } else if (loader && s + 1 < len) {
            x_s[li] = xr_n1;
        }
        __syncthreads();
        xr_n1 = xr_n2;
    }
    if (j < 40) {
        g_avgp[b * 80 + dir * 40 + j] = sum_p * __fdividef(1.f, (float)len);
        g_maxp[b * 80 + dir * 40 + j] = max_p;
        (dir ? g_hb1 : g_hf1)[b * HH + j] = h_s[j];
    }
}

// ---------------- Head: pool_cat -> fc1 -> leaky -> fc2 ----------------
__global__ void __launch_bounds__(128) fc_kernel(
    const float* __restrict__ fc1_b, const float* __restrict__ fc2_W,
    const float* __restrict__ fc2_b, float* __restrict__ out)
{
    int b = blockIdx.x, j = threadIdx.x;
    __shared__ float cat[320];
    for (int i = j; i < 320; i += 128) {
        float v;
        if (i < 40)       v = g_hb1[b * 40 + i];
        else if (i < 80)  v = g_hf1[b * 40 + (i - 40)];
        else if (i < 120) v = g_hb0[b * 40 + (i - 80)];
        else if (i < 160) v = g_hf0[b * 40 + (i - 120)];
        else if (i < 240) v = g_avgp[b * 80 + (i - 160)];
        else              v = g_maxp[b * 80 + (i - 240)];
        cat[i] = v;
    }
    __syncthreads();
    float acc = fc1_b[j];
    #pragma unroll 8
    for (int k = 0; k < 320; k++)
        acc = fmaf(g_fc1WT[k * 128 + j], cat[k], acc);
    float h = (acc >= 0.f) ? acc : 0.01f * acc;
    float p = h * fc2_W[j];
    #pragma unroll
    for (int o = 16; o > 0; o >>= 1) p += __shfl_down_sync(0xffffffffu, p, o);
    __shared__ float red[4];
    if ((j & 31) == 0) red[j >> 5] = p;
    __syncthreads();
    if (j == 0) out[b] = (red[0] + red[1] + red[2] + red[3]) + fc2_b[0];
}

// ---------------- Launch ----------------
extern "C" void kernel_launch(void* const* d_in, const int* in_sizes, int n_in,
                              void* d_out, int out_size)
{
    const int*   text     = (const int*)d_in[0];
    const int*   text_len = (const int*)d_in[1];
    const float* emb      = (const float*)d_in[2];
    const float* Wih0f = (const float*)d_in[3];
    const float* Whh0f = (const float*)d_in[4];
    const float* bih0f = (const float*)d_in[5];
    const float* bhh0f = (const float*)d_in[6];
    const float* Wih0b = (const float*)d_in[7];
    const float* Whh0b = (const float*)d_in[8];
    const float* bih0b = (const float*)d_in[9];
    const float* bhh0b = (const float*)d_in[10];
    const float* Wih1f = (const float*)d_in[11];
    const float* Whh1f = (const float*)d_in[12];
    const float* bih1f = (const float*)d_in[13];
    const float* bhh1f = (const float*)d_in[14];
    const float* Wih1b = (const float*)d_in[15];
    const float* Whh1b = (const float*)d_in[16];
    const float* bih1b = (const float*)d_in[17];
    const float* bhh1b = (const float*)d_in[18];
    const float* fc1_W = (const float*)d_in[19];
    const float* fc1_b = (const float*)d_in[20];
    const float* fc2_W = (const float*)d_in[21];
    const float* fc2_b = (const float*)d_in[22];
    float* out = (float*)d_out;

    prep_weights<<<160, 256>>>(Wih0f, Whh0f, bih0f, Wih0b, Whh0b, bih0b,
                               Wih1f, Whh1f, Wih1b, Whh1b, fc1_W);
    sort_kernel<<<1, BB>>>(text_len);
    embw_kernel<<<(VV + 63) / 64, 256>>>(emb);
    gru_layer0<<<dim3(BB, 2), 128>>>(text, text_len, bhh0f, bhh0b);
    gru_layer1<<<dim3(BB, 2), 128>>>(text_len, bih1f, bhh1f, bih1b, bhh1b);
    fc_kernel<<<BB, 128>>>(fc1_b, fc2_W, fc2_b, out);
}